// round 2
// baseline (speedup 1.0000x reference)
#include <cuda_runtime.h>

// DeltaSynapse: I[b,o] = sum_e Weff[b,e,o] * sum_d (Xd[d,b,e]*(Wshort[d,b,e]+1)) * delaymap[d,e,o]
// Weff[b,e,o] = sg[e,o]*(W[e,o]*(1-frac[e,o]) + Wlong[b,e,o]*frac[e,o])
// sg[e,o] = (W[e,o] > 0) ? sign(signs_pre[e]) : 0
//
// Shapes: D=8, B=16, N=2048. HBM-bound (~417 MB unique traffic).

#define NN 2048
#define BB 16
#define DD 8
#define ECHUNK 64
#define OTILE 256

__global__ void ds_zero_kernel(float* __restrict__ out, int n) {
    int i = blockIdx.x * blockDim.x + threadIdx.x;
    if (i < n) out[i] = 0.0f;
}

__global__ __launch_bounds__(256, 2) void ds_main_kernel(
    const float* __restrict__ W,         // (N,N)
    const float* __restrict__ Wlong,     // (B,N,N)
    const float* __restrict__ Wshort,    // (D,B,N)
    const float* __restrict__ Xd,        // (D,B,N)
    const float* __restrict__ delaymap,  // (D,N,N)
    const float* __restrict__ frac,      // (N,N)
    const float* __restrict__ signs_pre, // (N,)
    float* __restrict__ out)             // (B,N)
{
    __shared__ float coef[ECHUNK][DD * BB]; // [e_local][d*B + b]
    __shared__ float sgn_sh[ECHUNK];

    const int tid = threadIdx.x;
    const int o   = blockIdx.x * OTILE + tid;
    const int e0  = blockIdx.y * ECHUNK;

    // Cooperative preload of coef for this e-chunk.
    // idx -> (d, b, e_local) with e_local fastest => Xd/Wshort loads coalesced.
    for (int idx = tid; idx < DD * BB * ECHUNK; idx += 256) {
        int el = idx % ECHUNK;
        int b  = (idx / ECHUNK) % BB;
        int d  = idx / (ECHUNK * BB);
        int gi = (d * BB + b) * NN + (e0 + el);
        float x  = Xd[gi];
        float ws = Wshort[gi];
        coef[el][d * BB + b] = x * (ws + 1.0f);
    }
    if (tid < ECHUNK) {
        float sp = signs_pre[e0 + tid];
        sgn_sh[tid] = (sp > 0.0f) ? 1.0f : ((sp < 0.0f) ? -1.0f : 0.0f);
    }
    __syncthreads();

    float acc[BB];
#pragma unroll
    for (int b = 0; b < BB; b++) acc[b] = 0.0f;

    for (int el = 0; el < ECHUNK; el++) {
        const int e = e0 + el;
        const long base_eo = (long)e * NN + o;

        float w = W[base_eo];
        float f = frac[base_eo];
        float se = sgn_sh[el];
        float sg = (w > 0.0f) ? se : 0.0f;
        float cbase = sg * w * (1.0f - f);
        float fs    = sg * f;

        float dm[DD];
#pragma unroll
        for (int d = 0; d < DD; d++)
            dm[d] = delaymap[(long)d * NN * NN + base_eo];

        float wl[BB];
#pragma unroll
        for (int b = 0; b < BB; b++)
            wl[b] = Wlong[(long)b * NN * NN + base_eo];

#pragma unroll
        for (int b = 0; b < BB; b++) {
            float p = 0.0f;
#pragma unroll
            for (int d = 0; d < DD; d++)
                p = fmaf(dm[d], coef[el][d * BB + b], p);
            float weff = fmaf(fs, wl[b], cbase);
            acc[b] = fmaf(weff, p, acc[b]);
        }
    }

#pragma unroll
    for (int b = 0; b < BB; b++)
        atomicAdd(&out[b * NN + o], acc[b]);
}

extern "C" void kernel_launch(void* const* d_in, const int* in_sizes, int n_in,
                              void* d_out, int out_size) {
    const float* W         = (const float*)d_in[0];
    const float* Wlong     = (const float*)d_in[1];
    const float* Wshort    = (const float*)d_in[2];
    const float* Xd        = (const float*)d_in[3];
    const float* delaymap  = (const float*)d_in[4];
    const float* STDP_frac = (const float*)d_in[5];
    const float* signs_pre = (const float*)d_in[6];
    float* out = (float*)d_out;

    ds_zero_kernel<<<(BB * NN + 255) / 256, 256>>>(out, BB * NN);

    dim3 grid(NN / OTILE, NN / ECHUNK); // (8, 32)
    ds_main_kernel<<<grid, 256>>>(W, Wlong, Wshort, Xd, delaymap,
                                  STDP_frac, signs_pre, out);
}